// round 3
// baseline (speedup 1.0000x reference)
#include <cuda_runtime.h>
#include <cuda_fp16.h>
#include <cuda_pipeline.h>
#include <mma.h>

using namespace nvcuda;

// Problem constants
#define IN_DIM   4096
#define OUT_DIM  11008
#define BATCH    64
#define KT       64             // K-chunk per iteration
#define NCHUNKS  (IN_DIM / KT)  // 64
#define ROWS     64             // OUT rows per CTA
#define NTHREADS 256
#define LDS      72             // smem leading dim (64 + 8 halves pad, rows 16B-aligned)

// fp16 copy of x, filled by a pre-kernel each launch (deterministic).
__device__ __half g_xh[BATCH * IN_DIM];

__global__ void convert_x_kernel(const float* __restrict__ x) {
    int i = blockIdx.x * blockDim.x + threadIdx.x;
    if (i < BATCH * IN_DIM) {
        g_xh[i] = __float2half_rn(x[i]);
    }
}

__global__ __launch_bounds__(NTHREADS)
void q4k_gemm_kernel(const int*   __restrict__ packed,
                     const float* __restrict__ d,
                     const float* __restrict__ dmin,
                     const int*   __restrict__ scales,
                     const int*   __restrict__ mins,
                     float*       __restrict__ out)
{
    // Ping-pong buffers: 2 * (64*72 + 64*72) * 2B = 36864 B (< 48 KB static limit)
    __shared__ __half sW[2][ROWS][LDS];    // dequantized weight tile [out-row][k]
    __shared__ __half sX[2][BATCH][LDS];   // x tile                  [batch][k]

    const int tid    = threadIdx.x;
    const int warpId = tid >> 5;
    const int r0     = blockIdx.x * ROWS;         // first OUT row of this CTA

    // Dequant mapping: each thread owns 16 weights (half a Q4_K block) per chunk.
    const int drow = tid >> 2;        // 0..63 : row within tile
    const int seg  = tid & 3;         // 0..3  : which 16-wide segment of the 64 k
    const int grow = r0 + drow;       // global OUT row this thread dequants

    // Warp tiling of the 64x64 output: warp (m, n2), m in {0..3}*16, n2 in {0,1}*32
    const int m0  = (warpId & 3) * 16;
    const int nb0 = (warpId >> 2) * 32;

    wmma::fragment<wmma::accumulator, 16, 16, 16, float> acc[2];
    wmma::fill_fragment(acc[0], 0.0f);
    wmma::fill_fragment(acc[1], 0.0f);

    // --------- register pipeline state for the packed/scale stream ---------
    int4  pp[2];                 // 8 packed int32 = 16 weights
    float pd, pdm;
    int   psc, pmn;

    // Prologue: prefetch chunk 0 packed/scales, start x chunk 0 cp.async.
    {
        const int gk = seg * 16;
        const int s  = grow * (IN_DIM / 256) + (gk >> 8);
        const int blk = (gk >> 5) & 7;
        pd  = d[s];
        pdm = dmin[s];
        psc = scales[s * 8 + blk];
        pmn = mins[s * 8 + blk];
        const int4* p4 = reinterpret_cast<const int4*>(packed)
                       + ((grow * (IN_DIM / 2) + (gk >> 1)) >> 2);
        pp[0] = p4[0];
        pp[1] = p4[1];

        // x tile chunk 0: 64 batch x 64 k halves = 8 KB = 512 int4, 2 per thread
        #pragma unroll
        for (int i = 0; i < 2; i++) {
            int c  = tid + i * NTHREADS;  // 0..511
            int br = c >> 3;              // batch row (64/8 = 8 int4 chunks per row)
            int ch = c & 7;
            __pipeline_memcpy_async(&sX[0][br][ch * 8],
                                    g_xh + br * IN_DIM + ch * 8, 16);
        }
        __pipeline_commit();
    }

    for (int iter = 0; iter < NCHUNKS; iter++) {
        const int buf = iter & 1;

        // ---- Dequantize current chunk from registers into sW[buf] ----
        {
            const float A = pd * (float)psc * (1.0f / 945.0f);   // d * (sc/63) / 15
            const float B = pd * (float)pmn * (1.0f / 63.0f) + pdm;
            __half2* dst = reinterpret_cast<__half2*>(&sW[buf][drow][seg * 16]);
            #pragma unroll
            for (int t = 0; t < 2; t++) {
                const int vv[4] = {pp[t].x, pp[t].y, pp[t].z, pp[t].w};
                #pragma unroll
                for (int j = 0; j < 4; j++) {
                    int b  = vv[j];
                    float f0 = (float)(b & 15)        * A + B;   // low  -> even weight
                    float f1 = (float)((b >> 4) & 15) * A + B;   // high -> odd weight
                    dst[t * 4 + j] = __floats2half2_rn(f0, f1);
                }
            }
        }

        // ---- Prefetch next chunk's packed + scales (consumed after next BAR) ----
        if (iter + 1 < NCHUNKS) {
            const int gk = (iter + 1) * KT + seg * 16;
            const int s  = grow * (IN_DIM / 256) + (gk >> 8);
            const int blk = (gk >> 5) & 7;
            pd  = d[s];
            pdm = dmin[s];
            psc = scales[s * 8 + blk];
            pmn = mins[s * 8 + blk];
            const int4* p4 = reinterpret_cast<const int4*>(packed)
                           + ((grow * (IN_DIM / 2) + (gk >> 1)) >> 2);
            pp[0] = p4[0];
            pp[1] = p4[1];
        }

        // x tile for THIS chunk (issued last iteration / prologue) must be in.
        __pipeline_wait_prior(0);
        __syncthreads();   // single barrier per chunk

        // ---- Start x load for NEXT chunk into the other buffer (overlaps MMA).
        // Safe: the barrier above guarantees all warps completed MMA(iter-1),
        // the last reader of sX[buf^1]. ----
        if (iter + 1 < NCHUNKS) {
            const int k0n = (iter + 1) * KT;
            #pragma unroll
            for (int i = 0; i < 2; i++) {
                int c  = tid + i * NTHREADS;
                int br = c >> 3;
                int ch = c & 7;
                __pipeline_memcpy_async(&sX[buf ^ 1][br][ch * 8],
                                        g_xh + br * IN_DIM + k0n + ch * 8, 16);
            }
            __pipeline_commit();
        }

        // ---- MMA: each warp 16x32 output, 64/16 = 4 k-steps ----
        #pragma unroll
        for (int kk = 0; kk < KT; kk += 16) {
            wmma::fragment<wmma::matrix_a, 16, 16, 16, __half, wmma::row_major> a;
            wmma::load_matrix_sync(a, &sW[buf][m0][kk], LDS);

            #pragma unroll
            for (int t = 0; t < 2; t++) {
                wmma::fragment<wmma::matrix_b, 16, 16, 16, __half, wmma::col_major> b;
                wmma::load_matrix_sync(b, &sX[buf][nb0 + t * 16][kk], LDS);
                wmma::mma_sync(acc[t], a, b, acc[t]);
            }
        }
        // No trailing barrier: next iteration's dequant writes sW[buf^1],
        // whose last readers (MMA of iter-1) are ordered by the barrier above.
    }

    // ---- Epilogue: D(m=out-row, n=batch) -> out[n * OUT_DIM + (r0 + m)] ----
    #pragma unroll
    for (int t = 0; t < 2; t++) {
        float* ptr = out + (size_t)(nb0 + t * 16) * OUT_DIM + (r0 + m0);
        wmma::store_matrix_sync(ptr, acc[t], OUT_DIM, wmma::mem_col_major);
    }
}

extern "C" void kernel_launch(void* const* d_in, const int* in_sizes, int n_in,
                              void* d_out, int out_size) {
    const float* x      = (const float*)d_in[0];
    const int*   packed = (const int*)  d_in[1];
    const float* d      = (const float*)d_in[2];
    const float* dmin   = (const float*)d_in[3];
    const int*   scales = (const int*)  d_in[4];
    const int*   mins   = (const int*)  d_in[5];
    float*       out    = (float*)d_out;

    convert_x_kernel<<<(BATCH * IN_DIM + 255) / 256, 256>>>(x);
    q4k_gemm_kernel<<<OUT_DIM / ROWS, NTHREADS>>>(packed, d, dmin, scales, mins, out);
}

// round 6
// speedup vs baseline: 1.3705x; 1.3705x over previous
#include <cuda_runtime.h>
#include <cuda_fp16.h>
#include <cuda_pipeline.h>
#include <mma.h>

using namespace nvcuda;

// Problem constants
#define IN_DIM   4096
#define OUT_DIM  11008
#define BATCH    64
#define KSPLIT   4                      // split-K factor (more CTAs -> occupancy)
#define KSEG     (IN_DIM / KSPLIT)      // 1024 k per split
#define KT       64                     // K-chunk per iteration
#define NCHUNKS  (KSEG / KT)            // 16
#define ROWS     64                     // OUT rows per CTA
#define NTHREADS 256
#define LDS      72                     // smem leading dim (64 + 8 halves pad)

// fp16 copy of x, filled by a pre-kernel each launch (deterministic).
__device__ __half g_xh[BATCH * IN_DIM];
// Split-K partial sums: each element written exactly once per launch.
__device__ float  g_partial[KSPLIT][BATCH * OUT_DIM];

__global__ void convert_x_kernel(const float* __restrict__ x) {
    int i = blockIdx.x * blockDim.x + threadIdx.x;
    if (i < BATCH * IN_DIM) {
        g_xh[i] = __float2half_rn(x[i]);
    }
}

__global__ void reduce_kernel(float* __restrict__ out) {
    int i = blockIdx.x * blockDim.x + threadIdx.x;   // float4 index, 176128 total
    float4 a = reinterpret_cast<const float4*>(g_partial[0])[i];
    float4 b = reinterpret_cast<const float4*>(g_partial[1])[i];
    float4 c = reinterpret_cast<const float4*>(g_partial[2])[i];
    float4 e = reinterpret_cast<const float4*>(g_partial[3])[i];
    float4 r;
    r.x = (a.x + b.x) + (c.x + e.x);
    r.y = (a.y + b.y) + (c.y + e.y);
    r.z = (a.z + b.z) + (c.z + e.z);
    r.w = (a.w + b.w) + (c.w + e.w);
    reinterpret_cast<float4*>(out)[i] = r;
}

// minBlocksPerMultiprocessor=4 forces ptxas to keep regs <= 64 so the
// split-K occupancy target (4 CTA/SM = 32 warps) is guaranteed, not lucky.
__global__ __launch_bounds__(NTHREADS, 4)
void q4k_gemm_kernel(const int*   __restrict__ packed,
                     const float* __restrict__ d,
                     const float* __restrict__ dmin,
                     const int*   __restrict__ scales,
                     const int*   __restrict__ mins)
{
    // Ping-pong buffers: 2 * (64*72 + 64*72) * 2B = 36864 B
    __shared__ __half sW[2][ROWS][LDS];    // dequantized weight tile [out-row][k]
    __shared__ __half sX[2][BATCH][LDS];   // x tile                  [batch][k]

    const int tid    = threadIdx.x;
    const int warpId = tid >> 5;
    const int r0     = blockIdx.x * ROWS;          // first OUT row of this CTA
    const int split  = blockIdx.y;                 // k-split index
    const int kbase  = split * KSEG;               // first k of this split

    // Dequant mapping: each thread owns 16 weights per chunk.
    const int drow = tid >> 2;        // 0..63 : row within tile
    const int seg  = tid & 3;         // 0..3  : 16-wide segment of the 64 k
    const int grow = r0 + drow;       // global OUT row this thread dequants

    // Warp tiling of the 64x64 output: warp (m, n2), m in {0..3}*16, n2 in {0,1}*32
    const int m0  = (warpId & 3) * 16;
    const int nb0 = (warpId >> 2) * 32;

    wmma::fragment<wmma::accumulator, 16, 16, 16, float> acc[2];
    wmma::fill_fragment(acc[0], 0.0f);
    wmma::fill_fragment(acc[1], 0.0f);

    // --------- register pipeline state for the packed/scale stream ---------
    int4  pp[2];                 // 8 packed int32 = 16 weights
    float pd, pdm;
    int   psc, pmn;

    // Prologue: prefetch chunk 0 packed/scales, start x chunk 0 cp.async.
    {
        const int gk = kbase + seg * 16;
        const int s  = grow * (IN_DIM / 256) + (gk >> 8);
        const int blk = (gk >> 5) & 7;
        pd  = d[s];
        pdm = dmin[s];
        psc = scales[s * 8 + blk];
        pmn = mins[s * 8 + blk];
        const int4* p4 = reinterpret_cast<const int4*>(packed)
                       + ((grow * (IN_DIM / 2) + (gk >> 1)) >> 2);
        pp[0] = __ldcs(p4 + 0);    // evict-first: packed is a read-once stream
        pp[1] = __ldcs(p4 + 1);

        // x tile chunk 0: 64 batch x 64 k halves = 8 KB = 512 int4, 2 per thread
        #pragma unroll
        for (int i = 0; i < 2; i++) {
            int c  = tid + i * NTHREADS;  // 0..511
            int br = c >> 3;              // batch row
            int ch = c & 7;
            __pipeline_memcpy_async(&sX[0][br][ch * 8],
                                    g_xh + br * IN_DIM + kbase + ch * 8, 16);
        }
        __pipeline_commit();
    }

    for (int iter = 0; iter < NCHUNKS; iter++) {
        const int buf = iter & 1;

        // ---- Dequantize current chunk from registers into sW[buf] ----
        {
            const float A = pd * (float)psc * (1.0f / 945.0f);   // d * (sc/63) / 15
            const float B = pd * (float)pmn * (1.0f / 63.0f) + pdm;
            __half2* dst = reinterpret_cast<__half2*>(&sW[buf][drow][seg * 16]);
            #pragma unroll
            for (int t = 0; t < 2; t++) {
                const int vv[4] = {pp[t].x, pp[t].y, pp[t].z, pp[t].w};
                #pragma unroll
                for (int j = 0; j < 4; j++) {
                    int b  = vv[j];
                    float f0 = (float)(b & 15)        * A + B;   // low  -> even
                    float f1 = (float)((b >> 4) & 15) * A + B;   // high -> odd
                    dst[t * 4 + j] = __floats2half2_rn(f0, f1);
                }
            }
        }

        // ---- Prefetch next chunk's packed + scales (consumed after next BAR) ----
        if (iter + 1 < NCHUNKS) {
            const int gk = kbase + (iter + 1) * KT + seg * 16;
            const int s  = grow * (IN_DIM / 256) + (gk >> 8);
            const int blk = (gk >> 5) & 7;
            pd  = d[s];
            pdm = dmin[s];
            psc = scales[s * 8 + blk];
            pmn = mins[s * 8 + blk];
            const int4* p4 = reinterpret_cast<const int4*>(packed)
                           + ((grow * (IN_DIM / 2) + (gk >> 1)) >> 2);
            pp[0] = __ldcs(p4 + 0);
            pp[1] = __ldcs(p4 + 1);
        }

        // x tile for THIS chunk must be in.
        __pipeline_wait_prior(0);
        __syncthreads();   // single barrier per chunk

        // ---- Start x load for NEXT chunk into the other buffer (overlaps MMA).
        // Safe: barrier above ordered all readers of sX[buf^1] (MMA of iter-1). ----
        if (iter + 1 < NCHUNKS) {
            const int k0n = kbase + (iter + 1) * KT;
            #pragma unroll
            for (int i = 0; i < 2; i++) {
                int c  = tid + i * NTHREADS;
                int br = c >> 3;
                int ch = c & 7;
                __pipeline_memcpy_async(&sX[buf ^ 1][br][ch * 8],
                                        g_xh + br * IN_DIM + k0n + ch * 8, 16);
            }
            __pipeline_commit();
        }

        // ---- MMA: each warp 16x32 output, 64/16 = 4 k-steps ----
        #pragma unroll
        for (int kk = 0; kk < KT; kk += 16) {
            wmma::fragment<wmma::matrix_a, 16, 16, 16, __half, wmma::row_major> a;
            wmma::load_matrix_sync(a, &sW[buf][m0][kk], LDS);

            #pragma unroll
            for (int t = 0; t < 2; t++) {
                wmma::fragment<wmma::matrix_b, 16, 16, 16, __half, wmma::col_major> b;
                wmma::load_matrix_sync(b, &sX[buf][nb0 + t * 16][kk], LDS);
                wmma::mma_sync(acc[t], a, b, acc[t]);
            }
        }
    }

    // ---- Epilogue: D(m=out-row, n=batch) -> partial[split][n*OUT_DIM + (r0+m)] ----
    #pragma unroll
    for (int t = 0; t < 2; t++) {
        float* ptr = g_partial[split] + (size_t)(nb0 + t * 16) * OUT_DIM + (r0 + m0);
        wmma::store_matrix_sync(ptr, acc[t], OUT_DIM, wmma::mem_col_major);
    }
}

extern "C" void kernel_launch(void* const* d_in, const int* in_sizes, int n_in,
                              void* d_out, int out_size) {
    const float* x      = (const float*)d_in[0];
    const int*   packed = (const int*)  d_in[1];
    const float* d      = (const float*)d_in[2];
    const float* dmin   = (const float*)d_in[3];
    const int*   scales = (const int*)  d_in[4];
    const int*   mins   = (const int*)  d_in[5];
    float*       out    = (float*)d_out;

    convert_x_kernel<<<(BATCH * IN_DIM + 255) / 256, 256>>>(x);

    dim3 grid(OUT_DIM / ROWS, KSPLIT);   // 172 x 4 = 688 CTAs
    q4k_gemm_kernel<<<grid, NTHREADS>>>(packed, d, dmin, scales, mins);

    // 64*11008 / 4 floats per thread = 176128 threads = 688 blocks of 256
    reduce_kernel<<<(BATCH * OUT_DIM / 4) / 256, 256>>>(out);
}